// round 15
// baseline (speedup 1.0000x reference)
#include <cuda_runtime.h>

#define NN 64
#define CC 128
#define HH 64
#define WW 64
#define HID 8
#define NPLANE 9                       // 8 W_i2 rows + 1 bias plane
#define STAGES 8

typedef unsigned long long u64;

// Packed fp32x2 ops (Blackwell FFMA2 — PTX-only, ptxas never auto-fuses)
static __device__ __forceinline__ u64 f2fma(u64 a, u64 b, u64 c) {
    u64 d;
    asm("fma.rn.f32x2 %0, %1, %2, %3;" : "=l"(d) : "l"(a), "l"(b), "l"(c));
    return d;
}
static __device__ __forceinline__ u64 f2add(u64 a, u64 b) {
    u64 d;
    asm("add.rn.f32x2 %0, %1, %2;" : "=l"(d) : "l"(a), "l"(b));
    return d;
}
static __device__ __forceinline__ u64 f2pack(float lo, float hi) {
    u64 d;
    asm("mov.b64 %0, {%1, %2};" : "=l"(d) : "f"(lo), "f"(hi));
    return d;
}
static __device__ __forceinline__ float2 f2unpack(u64 s) {
    float lo, hi;
    asm("mov.b64 {%0, %1}, %2;" : "=f"(lo), "=f"(hi) : "l"(s));
    return make_float2(lo, hi);
}
static __device__ __forceinline__ unsigned smem_u32(const void* p) {
    unsigned a;
    asm("{ .reg .u64 tmp; cvta.to.shared.u64 tmp, %1; cvt.u32.u64 %0, tmp; }"
        : "=r"(a) : "l"(p));
    return a;
}
#define CP16(saddr, gptr) \
    asm volatile("cp.async.cg.shared.global [%0], [%1], 16;" \
                 :: "r"(saddr), "l"(gptr) : "memory")
#define CP_COMMIT() asm volatile("cp.async.commit_group;" ::: "memory")
#define CP_WAIT7()  asm volatile("cp.async.wait_group 7;" ::: "memory")

// Scratch (device globals). All fully rewritten every call -> deterministic.
__device__ float  g_hpart[NN][16][16];     // per-chunk proj partials (o1|i1)
__device__ float  g_ppart[NN][16][4];      // per-chunk per-wgroup sums
__device__ float  g_sp[NN][9];
__device__ float  g_co[NN][CC];
__device__ float4 g_y[NPLANE][NN * 1024];  // 9 reduced planes (float4 quads)
__device__ float  g_z[NN][HH][WW];         // final weighted combination

// ---------------------------------------------------------------------------
// Kernel A': SINGLE pass over x (134 MB), cp.async 8-stage ring, CHANNEL-
// SPLIT 2x: threads 0..63 handle channels 0..63 of their quad, threads
// 64..127 handle channels 64..127 of the SAME quads; halves merged via smem.
// Doubles chip-wide warps (131K threads -> ~20 warps/SM) to raise memory
// concurrency; per-thread loop drops to 64 iterations.
// Block = (chunk 0..15, n), 128 threads.
// ---------------------------------------------------------------------------
__global__ void __launch_bounds__(128, 5)
kA_fused(const float* __restrict__ x,
         const float* __restrict__ W_i2, const float* __restrict__ b_i2,
         const float* __restrict__ W_o1, const float* __restrict__ W_i1) {
    int chunk = blockIdx.x;            // 0..15
    int n     = blockIdx.y;
    int t     = threadIdx.x;           // 0..127
    int warp  = t >> 5;
    int lane  = t & 31;
    int half  = t >> 6;                // channel half
    int tq    = t & 63;                // quad within chunk

    __shared__ __align__(16) float4 sbuf[STAGES][128];  // 16 KB stage ring
    __shared__ u64 swA2[CC][NPLANE];   // (w,w) pairs
    __shared__ u64 swB2[CC][8];        // proj weight pairs
    __shared__ float stot[128];
    __shared__ float shp[4][16];

    for (int idx = t; idx < CC * NPLANE; idx += 128) {
        int c = idx / NPLANE, j = idx - c * NPLANE;
        float w = (j < 8) ? W_i2[j * CC + c] : b_i2[c];
        swA2[c][j] = f2pack(w, w);
    }
    for (int idx = t; idx < CC * 8; idx += 128) {
        int c = idx >> 3, k = idx & 7;
        float w0 = (k < 4) ? W_o1[c * HID + 2 * k]     : W_i1[c * HID + 2 * (k - 4)];
        float w1 = (k < 4) ? W_o1[c * HID + 2 * k + 1] : W_i1[c * HID + 2 * (k - 4) + 1];
        swB2[c][k] = f2pack(w0, w1);
    }
    __syncthreads();

    int q = chunk * 64 + tq;           // float4 index within plane (0..1023)
    const float4* xp = (const float4*)x + (size_t)n * CC * 1024
                     + (size_t)(half * 64) * 1024 + q;
    unsigned sb = smem_u32(&sbuf[0][0]) + (unsigned)t * 16u;

    u64 acc[2 * NPLANE];
#pragma unroll
    for (int j = 0; j < 2 * NPLANE; ++j) acc[j] = 0ull;
    u64 hp2[8];
#pragma unroll
    for (int j = 0; j < 8; ++j) hp2[j] = 0ull;
    float tot = 0.f;

    // prologue: stage local channels 0..6 (one commit-group per channel)
#pragma unroll
    for (int s = 0; s < STAGES - 1; ++s) {
        CP16(sb + (unsigned)(s << 11), xp + (size_t)s * 1024);
        CP_COMMIT();
    }

    for (int cl = 0; cl < 64; ++cl) {
        int cn = cl + STAGES - 1;
        if (cn < 64)
            CP16(sb + (unsigned)((cn & (STAGES - 1)) << 11),
                 xp + (size_t)cn * 1024);
        CP_COMMIT();                   // group index == local channel index
        CP_WAIT7();                    // stage cl complete

        float4 v = sbuf[cl & (STAGES - 1)][t];
        int ch = half * 64 + cl;
        u64 vlo = f2pack(v.x, v.y);
        u64 vhi = f2pack(v.z, v.w);

#pragma unroll
        for (int j = 0; j < NPLANE; ++j) {
            u64 w = swA2[ch][j];
            acc[2 * j]     = f2fma(w, vlo, acc[2 * j]);
            acc[2 * j + 1] = f2fma(w, vhi, acc[2 * j + 1]);
        }

        float2 sp2 = f2unpack(f2add(vlo, vhi));
        float s = sp2.x + sp2.y;
        tot += s;
        u64 s2 = f2pack(s, s);

#pragma unroll
        for (int j = 0; j < 8; ++j)
            hp2[j] = f2fma(swB2[ch][j], s2, hp2[j]);
    }

    // merge the two channel halves (ring is dead; reuse its smem)
    __syncthreads();
    u64 (*smerge)[2 * NPLANE] = reinterpret_cast<u64 (*)[2 * NPLANE]>(&sbuf[0][0]);
    if (half == 1) {
#pragma unroll
        for (int j = 0; j < 2 * NPLANE; ++j) smerge[tq][j] = acc[j];
    }
    __syncthreads();
    if (half == 0) {
#pragma unroll
        for (int j = 0; j < NPLANE; ++j) {
            float2 lo = f2unpack(f2add(acc[2 * j],     smerge[tq][2 * j]));
            float2 hi = f2unpack(f2add(acc[2 * j + 1], smerge[tq][2 * j + 1]));
            g_y[j][n * 1024 + q] = make_float4(lo.x, lo.y, hi.x, hi.y);
        }
    }

    // projections: warp-reduce (4 warps), then cross-warp combine
#pragma unroll
    for (int k = 0; k < 8; ++k) {
        float2 h = f2unpack(hp2[k]);
#pragma unroll
        for (int off = 16; off >= 1; off >>= 1) {
            h.x += __shfl_xor_sync(0xFFFFFFFFu, h.x, off);
            h.y += __shfl_xor_sync(0xFFFFFFFFu, h.y, off);
        }
        if (lane == 0) { shp[warp][2 * k] = h.x; shp[warp][2 * k + 1] = h.y; }
    }
    stot[t] = tot;
    __syncthreads();

    if (t < 16)
        g_hpart[n][chunk][t] = shp[0][t] + shp[1][t] + shp[2][t] + shp[3][t];

    // pool partials: quad tq -> local row r=tq/16, wgroup (tq%16)/4; both
    // halves' totals contribute.
    if (t < 4) {
        float s = 0.f;
#pragma unroll
        for (int r = 0; r < 4; ++r)
#pragma unroll
            for (int k = 0; k < 4; ++k) {
                int idx = r * 16 + t * 4 + k;
                s += stot[idx] + stot[64 + idx];
            }
        g_ppart[n][chunk][t] = s;
    }
}

// ---------------------------------------------------------------------------
// Fused kernel BZ: per block (n = blk/4, quarter = blk%4):
//   phase 1 (redundant x4 per n, identical results -> deterministic):
//     fold partials, finish MLPs, write g_co/g_sp, keep wz in smem
//   phase 2: z quarter = sum_j wz[j] * y_j  (L2-hot)
// grid 256 blocks x 256 threads.
// ---------------------------------------------------------------------------
__global__ void kBZ(const float* __restrict__ W_sp, const float* __restrict__ b_sp,
                    const float* __restrict__ b_o1, const float* __restrict__ b_i1,
                    const float* __restrict__ W_o2, const float* __restrict__ b_o2) {
    int blk = blockIdx.x;              // 0..255
    int n = blk >> 2, quarter = blk & 3;
    int t = threadIdx.x;               // 0..255

    __shared__ float sho[HID];
    __shared__ float sxs[16];
    __shared__ float swz[NPLANE];

    if (t < 16) {
        float s = 0.f;
#pragma unroll
        for (int k = 0; k < 16; ++k) s += g_hpart[n][k][t];
        s *= (1.f / (CC * 32.f));      // 1/4096 = 1/(H*W)
        if (t < 8) sho[t] = fmaxf(s + b_o1[t], 0.f);
        else       swz[t - 8] = fmaxf(s + b_i1[t - 8], 0.f);
    }
    if (t == 16) swz[8] = 1.f;         // bias-plane weight
    if (t >= 32 && t < 48) {           // pooled xs
        int p = t - 32;
        int hg = p >> 2, wg = p & 3;
        float s = 0.f;
#pragma unroll
        for (int k = 0; k < 4; ++k) s += g_ppart[n][hg * 4 + k][wg];
        sxs[p] = s * (1.f / (256.f * CC));
    }
    __syncthreads();

    if (t < CC) {                      // co (written 4x identically)
        float a = b_o2[t];
#pragma unroll
        for (int j = 0; j < HID; ++j)
            a += sho[j] * W_o2[j * CC + t];
        g_co[n][t] = a;
    }
    if (t < 9) {                       // sp (written 4x identically)
        float s = b_sp[t];
#pragma unroll
        for (int p = 0; p < 16; ++p) s += sxs[p] * W_sp[p * 9 + t];
        g_sp[n][t] = s;
    }

    // phase 2: this block's quarter of z
    int q = quarter * 256 + t;         // quad 0..1023
    float4 acc = make_float4(0.f, 0.f, 0.f, 0.f);
#pragma unroll
    for (int j = 0; j < NPLANE; ++j) {
        float4 v = g_y[j][n * 1024 + q];
        float s = swz[j];
        acc.x += s * v.x; acc.y += s * v.y;
        acc.z += s * v.z; acc.w += s * v.w;
    }
    ((float4*)g_z)[n * 1024 + q] = acc;
}

// ---------------------------------------------------------------------------
// Fused kernel DE: conv3x3 tile + 32-channel scaled store sweep.
// grid (8, NN, 4) = 2048 blocks, 256 threads. Streaming stores.
// ---------------------------------------------------------------------------
__global__ void kDE_convscale(float4* __restrict__ out) {
    int chunk = blockIdx.x;            // 0..7 -> output rows [chunk*8, +8)
    int n     = blockIdx.y;
    int ogrp  = blockIdx.z;            // 0..3 -> o in [ogrp*32, +32)
    int t     = threadIdx.x;           // 0..255

    __shared__ float sz[10][WW];
    __shared__ float st[8][WW];
    __shared__ float sco[32];
    __shared__ float ssp[9];

    int r0 = chunk * 8;

    if (t < 160) {
        int rr = t >> 4, qq = t & 15;
        int h = r0 - 1 + rr;
        float4 v = make_float4(0.f, 0.f, 0.f, 0.f);
        if (h >= 0 && h < HH)
            v = ((const float4*)g_z)[(n * HH + h) * 16 + qq];
        ((float4*)&sz[rr][0])[qq] = v;
    }
    if (t >= 192 && t < 224) sco[t - 192] = g_co[n][ogrp * 32 + (t - 192)];
    if (t >= 240 && t < 249) ssp[t - 240] = g_sp[n][t - 240];
    __syncthreads();

#pragma unroll
    for (int k = 0; k < 2; ++k) {
        int p = t + k * 256;           // 0..511
        int h = p >> 6, w = p & 63;
        float acc = 0.f;
#pragma unroll
        for (int kh = 0; kh < 3; ++kh) {
#pragma unroll
            for (int kw = 0; kw < 3; ++kw) {
                int ww = w + kw - 1;
                if (ww >= 0 && ww < WW)
                    acc += ssp[kh * 3 + kw] * sz[h + kh][ww];
            }
        }
        st[h][w] = acc;
    }
    __syncthreads();

    int q  = t & 127;
    int os = t >> 7;
    float4 v = ((const float4*)st)[q];
    int rr = q >> 4, qq = q & 15;

    int o0 = ogrp * 32 + os * 16;
    size_t base = ((size_t)n * CC + o0) * (HH * WW / 4)
                + (size_t)(r0 + rr) * 16 + qq;
#pragma unroll 4
    for (int o = 0; o < 16; ++o) {
        float s = sco[os * 16 + o];
        float4 ov;
        ov.x = v.x * s; ov.y = v.y * s; ov.z = v.z * s; ov.w = v.w * s;
        __stcs(&out[base + (size_t)o * (HH * WW / 4)], ov);
    }
}

// ---------------------------------------------------------------------------
extern "C" void kernel_launch(void* const* d_in, const int* in_sizes, int n_in,
                              void* d_out, int out_size) {
    const float* x    = (const float*)d_in[0];
    const float* W_sp = (const float*)d_in[1];
    const float* b_sp = (const float*)d_in[2];
    const float* W_o1 = (const float*)d_in[3];
    const float* b_o1 = (const float*)d_in[4];
    const float* W_o2 = (const float*)d_in[5];
    const float* b_o2 = (const float*)d_in[6];
    const float* W_i1 = (const float*)d_in[7];
    const float* b_i1 = (const float*)d_in[8];
    const float* W_i2 = (const float*)d_in[9];
    const float* b_i2 = (const float*)d_in[10];

    {
        dim3 g(16, NN);
        kA_fused<<<g, 128>>>(x, W_i2, b_i2, W_o1, W_i1);
    }
    kBZ<<<256, 256>>>(W_sp, b_sp, b_o1, b_i1, W_o2, b_o2);
    {
        dim3 g(8, NN, 4);
        kDE_convscale<<<g, 256>>>((float4*)d_out);
    }
}

// round 16
// speedup vs baseline: 1.4338x; 1.4338x over previous
#include <cuda_runtime.h>

#define NN 64
#define CC 128
#define HH 64
#define WW 64
#define HID 8
#define NPLANE 9                       // 8 W_i2 rows + 1 bias plane
#define STAGES 8
#define NCHUNK 8                       // 8 row-chunks of 8 rows each

typedef unsigned long long u64;

static __device__ __forceinline__ u64 f2fma(u64 a, u64 b, u64 c) {
    u64 d;
    asm("fma.rn.f32x2 %0, %1, %2, %3;" : "=l"(d) : "l"(a), "l"(b), "l"(c));
    return d;
}
static __device__ __forceinline__ u64 f2add(u64 a, u64 b) {
    u64 d;
    asm("add.rn.f32x2 %0, %1, %2;" : "=l"(d) : "l"(a), "l"(b));
    return d;
}
static __device__ __forceinline__ u64 f2pack(float lo, float hi) {
    u64 d;
    asm("mov.b64 %0, {%1, %2};" : "=l"(d) : "f"(lo), "f"(hi));
    return d;
}
static __device__ __forceinline__ float2 f2unpack(u64 s) {
    float lo, hi;
    asm("mov.b64 {%0, %1}, %2;" : "=f"(lo), "=f"(hi) : "l"(s));
    return make_float2(lo, hi);
}
static __device__ __forceinline__ unsigned smem_u32(const void* p) {
    unsigned a;
    asm("{ .reg .u64 tmp; cvta.to.shared.u64 tmp, %1; cvt.u32.u64 %0, tmp; }"
        : "=r"(a) : "l"(p));
    return a;
}
#define CP16(saddr, gptr) \
    asm volatile("cp.async.cg.shared.global [%0], [%1], 16;" \
                 :: "r"(saddr), "l"(gptr) : "memory")
#define CP_COMMIT() asm volatile("cp.async.commit_group;" ::: "memory")
#define CP_WAIT7()  asm volatile("cp.async.wait_group 7;" ::: "memory")

// Scratch (device globals). All fully rewritten every call -> deterministic.
__device__ float  g_hpart[NN][NCHUNK][16]; // per-chunk proj partials (o1|i1)
__device__ float  g_ppart[NN][NCHUNK][4];  // per-chunk per-wgroup sums
__device__ float  g_sp[NN][9];
__device__ float  g_co[NN][CC];
__device__ float4 g_y[NPLANE][NN * 1024];  // 9 reduced planes (float4 quads)
__device__ float  g_z[NN][HH][WW];         // final weighted combination

// ---------------------------------------------------------------------------
// Kernel A': SINGLE pass over x (134 MB), cp.async 8-stage ring, 2 QUADS
// (32B) per thread per channel: weight-LDS / wait / loop overhead amortized
// over twice the payload (fix for measured LSU/issue bound: L1=70%, DRAM=26%).
// Block = (chunk 0..7, n), 64 threads; chunk covers 8 rows = 128 quads;
// thread t owns quads q0 = chunk*128+t and q1 = q0+64.
// ---------------------------------------------------------------------------
__global__ void __launch_bounds__(64, 4)
kA_fused(const float* __restrict__ x,
         const float* __restrict__ W_i2, const float* __restrict__ b_i2,
         const float* __restrict__ W_o1, const float* __restrict__ W_i1) {
    int chunk = blockIdx.x;            // 0..7
    int n     = blockIdx.y;
    int t     = threadIdx.x;           // 0..63
    int warp  = t >> 5;
    int lane  = t & 31;

    __shared__ __align__(16) float4 sbuf[STAGES][128];  // 16 KB stage ring
    __shared__ u64 swA2[CC][NPLANE];   // (w,w) pairs
    __shared__ u64 swB2[CC][8];        // proj weight pairs
    __shared__ float stot[64];
    __shared__ float shp[2][16];

    for (int idx = t; idx < CC * NPLANE; idx += 64) {
        int c = idx / NPLANE, j = idx - c * NPLANE;
        float w = (j < 8) ? W_i2[j * CC + c] : b_i2[c];
        swA2[c][j] = f2pack(w, w);
    }
    for (int idx = t; idx < CC * 8; idx += 64) {
        int c = idx >> 3, k = idx & 7;
        float w0 = (k < 4) ? W_o1[c * HID + 2 * k]     : W_i1[c * HID + 2 * (k - 4)];
        float w1 = (k < 4) ? W_o1[c * HID + 2 * k + 1] : W_i1[c * HID + 2 * (k - 4) + 1];
        swB2[c][k] = f2pack(w0, w1);
    }
    __syncthreads();

    int q0 = chunk * 128 + t;          // first quad (0..1023); q1 = q0 + 64
    const float4* xp = (const float4*)x + (size_t)n * CC * 1024 + q0;
    unsigned sb = smem_u32(&sbuf[0][0]) + (unsigned)t * 16u;

    u64 accA[2 * NPLANE];              // quad q0 accumulators
    u64 accB[2 * NPLANE];              // quad q1 accumulators
#pragma unroll
    for (int j = 0; j < 2 * NPLANE; ++j) { accA[j] = 0ull; accB[j] = 0ull; }
    u64 hp2[8];
#pragma unroll
    for (int j = 0; j < 8; ++j) hp2[j] = 0ull;
    float tot = 0.f;

    // prologue: stage channels 0..6 (2 quads each), one group per channel
#pragma unroll
    for (int s = 0; s < STAGES - 1; ++s) {
        CP16(sb + (unsigned)(s << 11),          xp + (size_t)s * 1024);
        CP16(sb + (unsigned)(s << 11) + 1024u,  xp + (size_t)s * 1024 + 64);
        CP_COMMIT();
    }

    for (int c = 0; c < CC; ++c) {
        int cn = c + STAGES - 1;
        if (cn < CC) {
            unsigned dst = sb + (unsigned)((cn & (STAGES - 1)) << 11);
            CP16(dst,         xp + (size_t)cn * 1024);
            CP16(dst + 1024u, xp + (size_t)cn * 1024 + 64);
        }
        CP_COMMIT();                   // group index == channel index
        CP_WAIT7();                    // stage c complete

        float4 v0 = sbuf[c & (STAGES - 1)][t];
        float4 v1 = sbuf[c & (STAGES - 1)][t + 64];
        u64 a_lo = f2pack(v0.x, v0.y);
        u64 a_hi = f2pack(v0.z, v0.w);
        u64 b_lo = f2pack(v1.x, v1.y);
        u64 b_hi = f2pack(v1.z, v1.w);

#pragma unroll
        for (int j = 0; j < NPLANE; ++j) {
            u64 w = swA2[c][j];
            accA[2 * j]     = f2fma(w, a_lo, accA[2 * j]);
            accA[2 * j + 1] = f2fma(w, a_hi, accA[2 * j + 1]);
            accB[2 * j]     = f2fma(w, b_lo, accB[2 * j]);
            accB[2 * j + 1] = f2fma(w, b_hi, accB[2 * j + 1]);
        }

        float2 sp2 = f2unpack(f2add(f2add(a_lo, a_hi), f2add(b_lo, b_hi)));
        float s = sp2.x + sp2.y;       // 8 pixels' sum
        tot += s;
        u64 s2 = f2pack(s, s);

#pragma unroll
        for (int j = 0; j < 8; ++j)
            hp2[j] = f2fma(swB2[c][j], s2, hp2[j]);
    }

    // write the 9 reduced-plane quads (both quads)
#pragma unroll
    for (int j = 0; j < NPLANE; ++j) {
        float2 lo = f2unpack(accA[2 * j]);
        float2 hi = f2unpack(accA[2 * j + 1]);
        g_y[j][n * 1024 + q0] = make_float4(lo.x, lo.y, hi.x, hi.y);
        lo = f2unpack(accB[2 * j]);
        hi = f2unpack(accB[2 * j + 1]);
        g_y[j][n * 1024 + q0 + 64] = make_float4(lo.x, lo.y, hi.x, hi.y);
    }

    // projections: warp-reduce, then cross-warp combine
#pragma unroll
    for (int k = 0; k < 8; ++k) {
        float2 h = f2unpack(hp2[k]);
#pragma unroll
        for (int off = 16; off >= 1; off >>= 1) {
            h.x += __shfl_xor_sync(0xFFFFFFFFu, h.x, off);
            h.y += __shfl_xor_sync(0xFFFFFFFFu, h.y, off);
        }
        if (lane == 0) { shp[warp][2 * k] = h.x; shp[warp][2 * k + 1] = h.y; }
    }
    stot[t] = tot;
    __syncthreads();

    if (t < 16) g_hpart[n][chunk][t] = shp[0][t] + shp[1][t];

    // pool partials: quads q0/q1 share wgroup wg=(t%16)/4; all 8 chunk rows
    // fall in one pool row-group (16-row cells = 2 chunks) -> one partial
    // per (chunk, wg).
    if (t < 4) {
        float s = 0.f;
#pragma unroll
        for (int r = 0; r < 4; ++r)
#pragma unroll
            for (int k = 0; k < 4; ++k)
                s += stot[r * 16 + t * 4 + k];
        g_ppart[n][chunk][t] = s;
    }
}

// ---------------------------------------------------------------------------
// Fused kernel BZ: per block (n = blk/4, quarter = blk%4):
//   phase 1 (redundant x4 per n, identical results -> deterministic):
//     fold partials, finish MLPs, write g_co/g_sp, keep wz in smem
//   phase 2: z quarter = sum_j wz[j] * y_j  (L2-hot)
// grid 256 blocks x 256 threads.
// ---------------------------------------------------------------------------
__global__ void kBZ(const float* __restrict__ W_sp, const float* __restrict__ b_sp,
                    const float* __restrict__ b_o1, const float* __restrict__ b_i1,
                    const float* __restrict__ W_o2, const float* __restrict__ b_o2) {
    int blk = blockIdx.x;              // 0..255
    int n = blk >> 2, quarter = blk & 3;
    int t = threadIdx.x;               // 0..255

    __shared__ float sho[HID];
    __shared__ float sxs[16];
    __shared__ float swz[NPLANE];

    if (t < 16) {
        float s = 0.f;
#pragma unroll
        for (int k = 0; k < NCHUNK; ++k) s += g_hpart[n][k][t];
        s *= (1.f / (CC * 32.f));      // 1/4096 = 1/(H*W)
        if (t < 8) sho[t] = fmaxf(s + b_o1[t], 0.f);
        else       swz[t - 8] = fmaxf(s + b_i1[t - 8], 0.f);
    }
    if (t == 16) swz[8] = 1.f;         // bias-plane weight
    if (t >= 32 && t < 48) {           // pooled xs: cell = 2 chunks
        int p = t - 32;
        int hg = p >> 2, wg = p & 3;
        float s = g_ppart[n][hg * 2][wg] + g_ppart[n][hg * 2 + 1][wg];
        sxs[p] = s * (1.f / (256.f * CC));
    }
    __syncthreads();

    if (t < CC) {                      // co (written 4x identically)
        float a = b_o2[t];
#pragma unroll
        for (int j = 0; j < HID; ++j)
            a += sho[j] * W_o2[j * CC + t];
        g_co[n][t] = a;
    }
    if (t < 9) {                       // sp (written 4x identically)
        float s = b_sp[t];
#pragma unroll
        for (int p = 0; p < 16; ++p) s += sxs[p] * W_sp[p * 9 + t];
        g_sp[n][t] = s;
    }

    // phase 2: this block's quarter of z
    int q = quarter * 256 + t;         // quad 0..1023
    float4 acc = make_float4(0.f, 0.f, 0.f, 0.f);
#pragma unroll
    for (int j = 0; j < NPLANE; ++j) {
        float4 v = g_y[j][n * 1024 + q];
        float s = swz[j];
        acc.x += s * v.x; acc.y += s * v.y;
        acc.z += s * v.z; acc.w += s * v.w;
    }
    ((float4*)g_z)[n * 1024 + q] = acc;
}

// ---------------------------------------------------------------------------
// Fused kernel DE: conv3x3 tile + 32-channel scaled store sweep.
// grid (8, NN, 4) = 2048 blocks, 256 threads. Streaming stores.
// ---------------------------------------------------------------------------
__global__ void kDE_convscale(float4* __restrict__ out) {
    int chunk = blockIdx.x;            // 0..7 -> output rows [chunk*8, +8)
    int n     = blockIdx.y;
    int ogrp  = blockIdx.z;            // 0..3 -> o in [ogrp*32, +32)
    int t     = threadIdx.x;           // 0..255

    __shared__ float sz[10][WW];
    __shared__ float st[8][WW];
    __shared__ float sco[32];
    __shared__ float ssp[9];

    int r0 = chunk * 8;

    if (t < 160) {
        int rr = t >> 4, qq = t & 15;
        int h = r0 - 1 + rr;
        float4 v = make_float4(0.f, 0.f, 0.f, 0.f);
        if (h >= 0 && h < HH)
            v = ((const float4*)g_z)[(n * HH + h) * 16 + qq];
        ((float4*)&sz[rr][0])[qq] = v;
    }
    if (t >= 192 && t < 224) sco[t - 192] = g_co[n][ogrp * 32 + (t - 192)];
    if (t >= 240 && t < 249) ssp[t - 240] = g_sp[n][t - 240];
    __syncthreads();

#pragma unroll
    for (int k = 0; k < 2; ++k) {
        int p = t + k * 256;           // 0..511
        int h = p >> 6, w = p & 63;
        float acc = 0.f;
#pragma unroll
        for (int kh = 0; kh < 3; ++kh) {
#pragma unroll
            for (int kw = 0; kw < 3; ++kw) {
                int ww = w + kw - 1;
                if (ww >= 0 && ww < WW)
                    acc += ssp[kh * 3 + kw] * sz[h + kh][ww];
            }
        }
        st[h][w] = acc;
    }
    __syncthreads();

    int q  = t & 127;
    int os = t >> 7;
    float4 v = ((const float4*)st)[q];
    int rr = q >> 4, qq = q & 15;

    int o0 = ogrp * 32 + os * 16;
    size_t base = ((size_t)n * CC + o0) * (HH * WW / 4)
                + (size_t)(r0 + rr) * 16 + qq;
#pragma unroll 4
    for (int o = 0; o < 16; ++o) {
        float s = sco[os * 16 + o];
        float4 ov;
        ov.x = v.x * s; ov.y = v.y * s; ov.z = v.z * s; ov.w = v.w * s;
        __stcs(&out[base + (size_t)o * (HH * WW / 4)], ov);
    }
}

// ---------------------------------------------------------------------------
extern "C" void kernel_launch(void* const* d_in, const int* in_sizes, int n_in,
                              void* d_out, int out_size) {
    const float* x    = (const float*)d_in[0];
    const float* W_sp = (const float*)d_in[1];
    const float* b_sp = (const float*)d_in[2];
    const float* W_o1 = (const float*)d_in[3];
    const float* b_o1 = (const float*)d_in[4];
    const float* W_o2 = (const float*)d_in[5];
    const float* b_o2 = (const float*)d_in[6];
    const float* W_i1 = (const float*)d_in[7];
    const float* b_i1 = (const float*)d_in[8];
    const float* W_i2 = (const float*)d_in[9];
    const float* b_i2 = (const float*)d_in[10];

    {
        dim3 g(NCHUNK, NN);
        kA_fused<<<g, 64>>>(x, W_i2, b_i2, W_o1, W_i1);
    }
    kBZ<<<256, 256>>>(W_sp, b_sp, b_o1, b_i1, W_o2, b_o2);
    {
        dim3 g(8, NN, 4);
        kDE_convscale<<<g, 256>>>((float4*)d_out);
    }
}

// round 17
// speedup vs baseline: 1.4817x; 1.0334x over previous
#include <cuda_runtime.h>

#define NN 64
#define CC 128
#define HH 64
#define WW 64
#define HID 8
#define NPLANE 9                       // 8 W_i2 rows + 1 bias plane
#define STAGES 12                      // 24KB ring (48KB static-smem cap)
#define NCHUNK 8                       // 8 row-chunks of 8 rows each

typedef unsigned long long u64;

static __device__ __forceinline__ u64 f2fma(u64 a, u64 b, u64 c) {
    u64 d;
    asm("fma.rn.f32x2 %0, %1, %2, %3;" : "=l"(d) : "l"(a), "l"(b), "l"(c));
    return d;
}
static __device__ __forceinline__ u64 f2add(u64 a, u64 b) {
    u64 d;
    asm("add.rn.f32x2 %0, %1, %2;" : "=l"(d) : "l"(a), "l"(b));
    return d;
}
static __device__ __forceinline__ u64 f2pack(float lo, float hi) {
    u64 d;
    asm("mov.b64 %0, {%1, %2};" : "=l"(d) : "f"(lo), "f"(hi));
    return d;
}
static __device__ __forceinline__ float2 f2unpack(u64 s) {
    float lo, hi;
    asm("mov.b64 {%0, %1}, %2;" : "=f"(lo), "=f"(hi) : "l"(s));
    return make_float2(lo, hi);
}
static __device__ __forceinline__ unsigned smem_u32(const void* p) {
    unsigned a;
    asm("{ .reg .u64 tmp; cvta.to.shared.u64 tmp, %1; cvt.u32.u64 %0, tmp; }"
        : "=r"(a) : "l"(p));
    return a;
}
#define CP16(saddr, gptr) \
    asm volatile("cp.async.cg.shared.global [%0], [%1], 16;" \
                 :: "r"(saddr), "l"(gptr) : "memory")
#define CP_COMMIT() asm volatile("cp.async.commit_group;" ::: "memory")
#define CP_WAIT11() asm volatile("cp.async.wait_group 11;" ::: "memory")

// Scratch (device globals). All fully rewritten every call -> deterministic.
__device__ float  g_hpart[NN][NCHUNK][16]; // per-chunk proj partials (o1|i1)
__device__ float  g_ppart[NN][NCHUNK][4];  // per-chunk per-wgroup sums
__device__ float  g_sp[NN][9];
__device__ float  g_co[NN][CC];
__device__ float4 g_y[NPLANE][NN * 1024];  // 9 reduced planes (float4 quads)
__device__ float  g_z[NN][HH][WW];         // final weighted combination

// ---------------------------------------------------------------------------
// Kernel A': SINGLE pass over x (134 MB), cp.async 12-stage ring (deepened
// from 8: in-flight bytes 7MB -> 11MB chip-wide; R14/R16 both measured
// ~3.3TB/s at the same 7MB in flight -> depth is the binding invariant),
// 2 quads (32B) per thread per channel.
// Block = (chunk 0..7, n), 64 threads; chunk covers 8 rows = 128 quads;
// thread t owns quads q0 = chunk*128+t and q1 = q0+64.
// ---------------------------------------------------------------------------
__global__ void __launch_bounds__(64, 4)
kA_fused(const float* __restrict__ x,
         const float* __restrict__ W_i2, const float* __restrict__ b_i2,
         const float* __restrict__ W_o1, const float* __restrict__ W_i1) {
    int chunk = blockIdx.x;            // 0..7
    int n     = blockIdx.y;
    int t     = threadIdx.x;           // 0..63
    int warp  = t >> 5;
    int lane  = t & 31;

    __shared__ __align__(16) float4 sbuf[STAGES][128];  // 24 KB stage ring
    __shared__ u64 swA2[CC][NPLANE];   // (w,w) pairs
    __shared__ u64 swB2[CC][8];        // proj weight pairs
    __shared__ float stot[64];
    __shared__ float shp[2][16];

    for (int idx = t; idx < CC * NPLANE; idx += 64) {
        int c = idx / NPLANE, j = idx - c * NPLANE;
        float w = (j < 8) ? W_i2[j * CC + c] : b_i2[c];
        swA2[c][j] = f2pack(w, w);
    }
    for (int idx = t; idx < CC * 8; idx += 64) {
        int c = idx >> 3, k = idx & 7;
        float w0 = (k < 4) ? W_o1[c * HID + 2 * k]     : W_i1[c * HID + 2 * (k - 4)];
        float w1 = (k < 4) ? W_o1[c * HID + 2 * k + 1] : W_i1[c * HID + 2 * (k - 4) + 1];
        swB2[c][k] = f2pack(w0, w1);
    }
    __syncthreads();

    int q0 = chunk * 128 + t;          // first quad (0..1023); q1 = q0 + 64
    const float4* xp = (const float4*)x + (size_t)n * CC * 1024 + q0;
    unsigned sb = smem_u32(&sbuf[0][0]) + (unsigned)t * 16u;

    u64 accA[2 * NPLANE];              // quad q0 accumulators
    u64 accB[2 * NPLANE];              // quad q1 accumulators
#pragma unroll
    for (int j = 0; j < 2 * NPLANE; ++j) { accA[j] = 0ull; accB[j] = 0ull; }
    u64 hp2[8];
#pragma unroll
    for (int j = 0; j < 8; ++j) hp2[j] = 0ull;
    float tot = 0.f;

    // prologue: stage channels 0..10 (2 quads each), one group per channel
#pragma unroll
    for (int s = 0; s < STAGES - 1; ++s) {
        CP16(sb + (unsigned)(s * 2048),         xp + (size_t)s * 1024);
        CP16(sb + (unsigned)(s * 2048) + 1024u, xp + (size_t)s * 1024 + 64);
        CP_COMMIT();
    }

    int rs = 0;                        // read stage  (= c % 12, wrap counter)
    for (int c = 0; c < CC; ++c) {
        int cn = c + STAGES - 1;       // channel to stage this iteration
        int ws = rs - 1; if (ws < 0) ws = STAGES - 1;  // = cn % 12
        if (cn < CC) {
            unsigned dst = sb + (unsigned)(ws * 2048);
            CP16(dst,         xp + (size_t)cn * 1024);
            CP16(dst + 1024u, xp + (size_t)cn * 1024 + 64);
        }
        CP_COMMIT();                   // group index == channel index
        CP_WAIT11();                   // stage c complete (11 groups in flight)

        float4 v0 = sbuf[rs][t];
        float4 v1 = sbuf[rs][t + 64];
        if (++rs == STAGES) rs = 0;
        u64 a_lo = f2pack(v0.x, v0.y);
        u64 a_hi = f2pack(v0.z, v0.w);
        u64 b_lo = f2pack(v1.x, v1.y);
        u64 b_hi = f2pack(v1.z, v1.w);

#pragma unroll
        for (int j = 0; j < NPLANE; ++j) {
            u64 w = swA2[c][j];
            accA[2 * j]     = f2fma(w, a_lo, accA[2 * j]);
            accA[2 * j + 1] = f2fma(w, a_hi, accA[2 * j + 1]);
            accB[2 * j]     = f2fma(w, b_lo, accB[2 * j]);
            accB[2 * j + 1] = f2fma(w, b_hi, accB[2 * j + 1]);
        }

        float2 sp2 = f2unpack(f2add(f2add(a_lo, a_hi), f2add(b_lo, b_hi)));
        float s = sp2.x + sp2.y;       // 8 pixels' sum
        tot += s;
        u64 s2 = f2pack(s, s);

#pragma unroll
        for (int j = 0; j < 8; ++j)
            hp2[j] = f2fma(swB2[c][j], s2, hp2[j]);
    }

    // write the 9 reduced-plane quads (both quads)
#pragma unroll
    for (int j = 0; j < NPLANE; ++j) {
        float2 lo = f2unpack(accA[2 * j]);
        float2 hi = f2unpack(accA[2 * j + 1]);
        g_y[j][n * 1024 + q0] = make_float4(lo.x, lo.y, hi.x, hi.y);
        lo = f2unpack(accB[2 * j]);
        hi = f2unpack(accB[2 * j + 1]);
        g_y[j][n * 1024 + q0 + 64] = make_float4(lo.x, lo.y, hi.x, hi.y);
    }

    // projections: warp-reduce, then cross-warp combine
#pragma unroll
    for (int k = 0; k < 8; ++k) {
        float2 h = f2unpack(hp2[k]);
#pragma unroll
        for (int off = 16; off >= 1; off >>= 1) {
            h.x += __shfl_xor_sync(0xFFFFFFFFu, h.x, off);
            h.y += __shfl_xor_sync(0xFFFFFFFFu, h.y, off);
        }
        if (lane == 0) { shp[warp][2 * k] = h.x; shp[warp][2 * k + 1] = h.y; }
    }
    stot[t] = tot;
    __syncthreads();

    if (t < 16) g_hpart[n][chunk][t] = shp[0][t] + shp[1][t];

    // pool partials: quads q0/q1 share wgroup wg=(t%16)/4.
    if (t < 4) {
        float s = 0.f;
#pragma unroll
        for (int r = 0; r < 4; ++r)
#pragma unroll
            for (int k = 0; k < 4; ++k)
                s += stot[r * 16 + t * 4 + k];
        g_ppart[n][chunk][t] = s;
    }
}

// ---------------------------------------------------------------------------
// Fused kernel BZ: per block (n = blk/4, quarter = blk%4):
//   phase 1 (redundant x4 per n, identical results -> deterministic):
//     fold partials, finish MLPs, write g_co/g_sp, keep wz in smem
//   phase 2: z quarter = sum_j wz[j] * y_j  (L2-hot)
// grid 256 blocks x 256 threads.
// ---------------------------------------------------------------------------
__global__ void kBZ(const float* __restrict__ W_sp, const float* __restrict__ b_sp,
                    const float* __restrict__ b_o1, const float* __restrict__ b_i1,
                    const float* __restrict__ W_o2, const float* __restrict__ b_o2) {
    int blk = blockIdx.x;              // 0..255
    int n = blk >> 2, quarter = blk & 3;
    int t = threadIdx.x;               // 0..255

    __shared__ float sho[HID];
    __shared__ float sxs[16];
    __shared__ float swz[NPLANE];

    if (t < 16) {
        float s = 0.f;
#pragma unroll
        for (int k = 0; k < NCHUNK; ++k) s += g_hpart[n][k][t];
        s *= (1.f / (CC * 32.f));      // 1/4096 = 1/(H*W)
        if (t < 8) sho[t] = fmaxf(s + b_o1[t], 0.f);
        else       swz[t - 8] = fmaxf(s + b_i1[t - 8], 0.f);
    }
    if (t == 16) swz[8] = 1.f;         // bias-plane weight
    if (t >= 32 && t < 48) {           // pooled xs: cell = 2 chunks
        int p = t - 32;
        int hg = p >> 2, wg = p & 3;
        float s = g_ppart[n][hg * 2][wg] + g_ppart[n][hg * 2 + 1][wg];
        sxs[p] = s * (1.f / (256.f * CC));
    }
    __syncthreads();

    if (t < CC) {                      // co (written 4x identically)
        float a = b_o2[t];
#pragma unroll
        for (int j = 0; j < HID; ++j)
            a += sho[j] * W_o2[j * CC + t];
        g_co[n][t] = a;
    }
    if (t < 9) {                       // sp (written 4x identically)
        float s = b_sp[t];
#pragma unroll
        for (int p = 0; p < 16; ++p) s += sxs[p] * W_sp[p * 9 + t];
        g_sp[n][t] = s;
    }

    // phase 2: this block's quarter of z
    int q = quarter * 256 + t;         // quad 0..1023
    float4 acc = make_float4(0.f, 0.f, 0.f, 0.f);
#pragma unroll
    for (int j = 0; j < NPLANE; ++j) {
        float4 v = g_y[j][n * 1024 + q];
        float s = swz[j];
        acc.x += s * v.x; acc.y += s * v.y;
        acc.z += s * v.z; acc.w += s * v.w;
    }
    ((float4*)g_z)[n * 1024 + q] = acc;
}

// ---------------------------------------------------------------------------
// Fused kernel DE: conv3x3 tile + 32-channel scaled store sweep.
// grid (8, NN, 4) = 2048 blocks, 256 threads. Streaming stores.
// ---------------------------------------------------------------------------
__global__ void kDE_convscale(float4* __restrict__ out) {
    int chunk = blockIdx.x;            // 0..7 -> output rows [chunk*8, +8)
    int n     = blockIdx.y;
    int ogrp  = blockIdx.z;            // 0..3 -> o in [ogrp*32, +32)
    int t     = threadIdx.x;           // 0..255

    __shared__ float sz[10][WW];
    __shared__ float st[8][WW];
    __shared__ float sco[32];
    __shared__ float ssp[9];

    int r0 = chunk * 8;

    if (t < 160) {
        int rr = t >> 4, qq = t & 15;
        int h = r0 - 1 + rr;
        float4 v = make_float4(0.f, 0.f, 0.f, 0.f);
        if (h >= 0 && h < HH)
            v = ((const float4*)g_z)[(n * HH + h) * 16 + qq];
        ((float4*)&sz[rr][0])[qq] = v;
    }
    if (t >= 192 && t < 224) sco[t - 192] = g_co[n][ogrp * 32 + (t - 192)];
    if (t >= 240 && t < 249) ssp[t - 240] = g_sp[n][t - 240];
    __syncthreads();

#pragma unroll
    for (int k = 0; k < 2; ++k) {
        int p = t + k * 256;           // 0..511
        int h = p >> 6, w = p & 63;
        float acc = 0.f;
#pragma unroll
        for (int kh = 0; kh < 3; ++kh) {
#pragma unroll
            for (int kw = 0; kw < 3; ++kw) {
                int ww = w + kw - 1;
                if (ww >= 0 && ww < WW)
                    acc += ssp[kh * 3 + kw] * sz[h + kh][ww];
            }
        }
        st[h][w] = acc;
    }
    __syncthreads();

    int q  = t & 127;
    int os = t >> 7;
    float4 v = ((const float4*)st)[q];
    int rr = q >> 4, qq = q & 15;

    int o0 = ogrp * 32 + os * 16;
    size_t base = ((size_t)n * CC + o0) * (HH * WW / 4)
                + (size_t)(r0 + rr) * 16 + qq;
#pragma unroll 4
    for (int o = 0; o < 16; ++o) {
        float s = sco[os * 16 + o];
        float4 ov;
        ov.x = v.x * s; ov.y = v.y * s; ov.z = v.z * s; ov.w = v.w * s;
        __stcs(&out[base + (size_t)o * (HH * WW / 4)], ov);
    }
}

// ---------------------------------------------------------------------------
extern "C" void kernel_launch(void* const* d_in, const int* in_sizes, int n_in,
                              void* d_out, int out_size) {
    const float* x    = (const float*)d_in[0];
    const float* W_sp = (const float*)d_in[1];
    const float* b_sp = (const float*)d_in[2];
    const float* W_o1 = (const float*)d_in[3];
    const float* b_o1 = (const float*)d_in[4];
    const float* W_o2 = (const float*)d_in[5];
    const float* b_o2 = (const float*)d_in[6];
    const float* W_i1 = (const float*)d_in[7];
    const float* b_i1 = (const float*)d_in[8];
    const float* W_i2 = (const float*)d_in[9];
    const float* b_i2 = (const float*)d_in[10];

    {
        dim3 g(NCHUNK, NN);
        kA_fused<<<g, 64>>>(x, W_i2, b_i2, W_o1, W_i1);
    }
    kBZ<<<256, 256>>>(W_sp, b_sp, b_o1, b_i1, W_o2, b_o2);
    {
        dim3 g(8, NN, 4);
        kDE_convscale<<<g, 256>>>((float4*)d_out);
    }
}